// round 15
// baseline (speedup 1.0000x reference)
#include <cuda_runtime.h>
#include <cuda_fp16.h>
#include <cstdint>

#define MAXN 100000
#define EPB  256            // edges per block
#define NTHR 256

typedef unsigned long long ull;

// ---------------- device scratch ----------------
__device__ __half d_q[(size_t)MAXN * 64];                // q[n][h*16+c] fp16, 12.8 MB
__device__ float d_denom[MAXN * 4];                      // per (node, head)
__device__ __align__(16) __half d_Bimg[2 * 192 * 72];    // [hi(192 cols) | lo(192 cols)][k pad 72]
__device__ int g_is64;

// ---------------- helpers ----------------
__device__ __forceinline__ void red4(float* p, float4 v) {
    asm volatile("red.global.add.v4.f32 [%0], {%1, %2, %3, %4};"
                 :: "l"(p), "f"(v.x), "f"(v.y), "f"(v.z), "f"(v.w) : "memory");
}
__device__ __forceinline__ long long load_idx(const void* p, long long i) {
    if (g_is64) return ((const long long*)p)[i];
    return (long long)((const int*)p)[i];
}
__device__ __forceinline__ uint32_t smem_u32(const void* p) {
    uint32_t a;
    asm("{ .reg .u64 t; cvta.to.shared.u64 t, %1; cvt.u32.u64 %0, t; }" : "=r"(a) : "l"(p));
    return a;
}
__device__ __forceinline__ uint32_t pack_h2(float a, float b) {
    __half2 h = __floats2half2_rn(a, b);
    return *(uint32_t*)&h;
}
__device__ __forceinline__ ull pk2(float lo, float hi) {
    ull r; asm("mov.b64 %0, {%1, %2};" : "=l"(r) : "f"(lo), "f"(hi)); return r;
}
__device__ __forceinline__ float2 upk2(ull v) {
    float2 r; asm("mov.b64 {%0, %1}, %2;" : "=f"(r.x), "=f"(r.y) : "l"(v)); return r;
}
#define FMA2(acc, a, b) asm("fma.rn.f32x2 %0, %1, %2, %0;" : "+l"(acc) : "l"(a), "l"(b))

__device__ __forceinline__ void mma16816(float c[4], const uint32_t a[4],
                                         uint32_t b0, uint32_t b1) {
    asm volatile("mma.sync.aligned.m16n8k16.row.col.f32.f16.f16.f32 "
                 "{%0,%1,%2,%3}, {%4,%5,%6,%7}, {%8,%9}, {%0,%1,%2,%3};"
                 : "+f"(c[0]), "+f"(c[1]), "+f"(c[2]), "+f"(c[3])
                 : "r"(a[0]), "r"(a[1]), "r"(a[2]), "r"(a[3]), "r"(b0), "r"(b1));
}
#define LDMX4(r, a)                                                        \
    asm volatile("ldmatrix.sync.aligned.m8n8.x4.shared.b16 {%0,%1,%2,%3}, [%4];" \
        : "=r"((r)[0]), "=r"((r)[1]), "=r"((r)[2]), "=r"((r)[3]) : "r"(a))
#define LDMX2(r, a)                                                        \
    asm volatile("ldmatrix.sync.aligned.m8n8.x2.shared.b16 {%0,%1}, [%2];" \
        : "=r"((r)[0]), "=r"((r)[1]) : "r"(a))

// ---------------- smem layout (bytes) — identical to R10/R14 ----------------
#define SM_SRC 0                       // int[256]            1024
#define SM_BE  1024                    // float[64]           256
#define SM_ATT 1280                    // float[256*4]        4096
#define SM_BHI 5376                    // half[192][72]       27648  (cols 0..191, hi)
#define SM_BLO 33024                   // half[128][72]       18432  (cols 0..127, lo)
#define SM_AHI 51456                   // half[256][72]       36864  (Z in plain fp16)
#define SMEM_BYTES 88320

// ================= kernel 1: fused setup (detect + zero + B image + q) =================
__global__ void __launch_bounds__(256) setup_kernel(const float* __restrict__ x,
                                                    const int*   __restrict__ eix32,
                                                    const float* __restrict__ Wq,
                                                    const float* __restrict__ Wv,
                                                    const float* __restrict__ We,
                                                    const float* __restrict__ Wk,
                                                    float4* __restrict__ out,
                                                    int Nn) {
    int t = threadIdx.x;

    // block 0: dtype detect + fp16 hi/lo split B image (cols 0..63 Wv, 64..127 We, 128..191 Wk)
    if (blockIdx.x == 0) {
        if (t == 0) {
            int any = 0;
            for (int i = 1; i < 256; i += 2) any |= eix32[i];
            g_is64 = (any == 0) ? 1 : 0;
        }
        if (t < 192) {
            int n = t;
            const float* W = (n < 64) ? Wv : ((n < 128) ? We : Wk);
            int nn = n & 63;
            for (int k = 0; k < 64; k++) {
                float w = W[k * 64 + nn];
                __half h = __float2half_rn(w);
                __half l = __float2half_rn(w - __half2float(h));
                d_Bimg[n * 72 + k]            = h;
                d_Bimg[192 * 72 + n * 72 + k] = l;
            }
        }
    }

    // zero out-accumulator + denom (grid-stride)
    {
        int i = blockIdx.x * blockDim.x + t;
        int st = gridDim.x * blockDim.x;
        float4 z = make_float4(0.f, 0.f, 0.f, 0.f);
        int n4 = Nn * 16;
        for (int j = i; j < n4; j += st) out[j] = z;
        float4* dn = (float4*)d_denom;
        for (int j = i; j < Nn; j += st) dn[j] = z;
    }

    // ---- q = x @ Wq (fp16 out), 64-node tiles, FMA2-based ----
    __shared__ float sWq[64 * 64];          // 16 KB
    __shared__ float sx[64 * 65];           // 16.25 KB, padded stride
    for (int i = t; i < 1024; i += 256) ((float4*)sWq)[i] = ((const float4*)Wq)[i];

    int nloc = t >> 2;                      // 0..63: node within tile
    int c0 = (t & 3) * 16;                  // col group

    for (int n0 = blockIdx.x * 64; n0 < Nn; n0 += gridDim.x * 64) {
        __syncthreads();
        // stage x tile: 64 rows x 64 floats, coalesced read, padded store
        for (int i = t; i < 1024; i += 256) {
            int row = i >> 4, c4 = (i & 15) * 4;
            float4 v = (n0 + row < Nn) ? ((const float4*)x)[(size_t)(n0 + row) * 16 + (i & 15)]
                                       : make_float4(0.f, 0.f, 0.f, 0.f);
            float* dst = sx + row * 65 + c4;
            dst[0] = v.x; dst[1] = v.y; dst[2] = v.z; dst[3] = v.w;
        }
        __syncthreads();

        int n = n0 + nloc;
        if (n >= Nn) continue;

        ull acc[8];
        #pragma unroll
        for (int i = 0; i < 8; i++) acc[i] = 0ull;

        const float* xr = sx + nloc * 65;
        #pragma unroll 4
        for (int d = 0; d < 64; d++) {
            float xv = xr[d];
            ull xv2 = pk2(xv, xv);
            const uint4* wr = (const uint4*)&sWq[d * 64 + c0];
            #pragma unroll
            for (int i = 0; i < 4; i++) {
                uint4 wq = wr[i];
                ull w0 = ((ull)wq.y << 32) | wq.x;
                ull w1 = ((ull)wq.w << 32) | wq.z;
                FMA2(acc[2 * i], xv2, w0);
                FMA2(acc[2 * i + 1], xv2, w1);
            }
        }

        uint32_t* qo = (uint32_t*)(d_q + (size_t)n * 64 + c0);
        #pragma unroll
        for (int i = 0; i < 8; i++) {
            float2 p = upk2(acc[i]);
            qo[i] = pack_h2(p.x, p.y);
        }
    }
}

// ================= kernel 2: fused edge pass (R14 — unchanged) =================
__global__ void __launch_bounds__(NTHR, 2) edge_kernel(const float* __restrict__ x,
                                                       const void*  __restrict__ eidx,
                                                       const float* __restrict__ ea,
                                                       const float* __restrict__ be,
                                                       float* __restrict__ outp,
                                                       float* __restrict__ eo,
                                                       long long Etot) {
    extern __shared__ __align__(16) char smem[];
    uint32_t smb = smem_u32(smem);
    int t = threadIdx.x, w = t >> 5, l = t & 31;
    int g = l >> 2, t4 = l & 3;

    int*   ssrc = (int*)(smem + SM_SRC);
    float* sbe  = (float*)(smem + SM_BE);
    float* satt = (float*)(smem + SM_ATT);

    long long ebase = (long long)blockIdx.x * EPB;

    // ---- B copy: contiguous prefix of d_Bimg = hi(1728 uint4) + lo cols 0..127 (1152 uint4) ----
    {
        const uint4* bs = (const uint4*)d_Bimg;
        uint4* bd = (uint4*)(smem + SM_BHI);
        #pragma unroll
        for (int i = 0; i < 12; i++) {
            int idx = t + NTHR * i;
            if (idx < 2880) bd[idx] = bs[idx];
        }
    }
    if (t < 64) sbe[t] = be[t];

    // ---- A build: 8 lanes per edge, coalesced. Z = ea * x[nbr] in plain fp16 ----
    {
        int oct = t & 7;
        int elb = t >> 3;                     // 0..31
        #pragma unroll
        for (int p = 0; p < 8; p++) {
            int eb = elb + 32 * p;            // edge within block
            long long e = ebase + eb;
            bool valid = (e < Etot);
            int src = 0; long long nbr = 0;
            if (valid) { src = (int)load_idx(eidx, e); nbr = load_idx(eidx, Etot + e); }
            if (oct == 0) ssrc[eb] = src;
            #pragma unroll
            for (int h2 = 0; h2 < 2; h2++) {
                float4 a4, x4;
                if (valid) {
                    a4 = *(const float4*)(ea + (size_t)e * 64 + h2 * 32 + oct * 4);
                    x4 = *(const float4*)(x + (size_t)nbr * 64 + h2 * 32 + oct * 4);
                } else {
                    a4 = make_float4(0.f, 0.f, 0.f, 0.f);
                    x4 = a4;
                }
                uint2 hv = make_uint2(pack_h2(a4.x * x4.x, a4.y * x4.y),
                                      pack_h2(a4.z * x4.z, a4.w * x4.w));
                *(uint2*)(smem + SM_AHI + (uint32_t)eb * 144 + h2 * 64 + oct * 8) = hv;
            }
        }
    }
    __syncthreads();

    // ---------------- per-warp: rows rb .. rb+31 (2 m-tiles) ----------------
    int rb = w * 32;

    int  srow[2][2];
    bool vrow[2][2];
    #pragma unroll
    for (int mt = 0; mt < 2; mt++)
        #pragma unroll
        for (int r = 0; r < 2; r++) {
            int row = rb + mt * 16 + g + 8 * r;
            srow[mt][r] = ssrc[row];
            vrow[mt][r] = (ebase + row) < Etot;
        }

    // ---- A fragments via ldmatrix.x4 (hi only) ----
    uint32_t afh[2][4][4];
    {
        uint32_t rowsel = (uint32_t)(l & 15);
        uint32_t koff = (uint32_t)(l >> 4) * 16;
        #pragma unroll
        for (int mt = 0; mt < 2; mt++) {
            uint32_t ab = smb + SM_AHI + (rb + mt * 16 + rowsel) * 144 + koff;
            #pragma unroll
            for (int ks = 0; ks < 4; ks++)
                LDMX4(afh[mt][ks], ab + ks * 32);
        }
    }

    // B per-lane bases (lanes 0-15 meaningful for x2)
    uint32_t lane_off = (uint32_t)(l & 7) * 144 + (uint32_t)((l >> 3) & 1) * 16;
    uint32_t bbh = smb + SM_BHI + lane_off;
    uint32_t bbl = smb + SM_BLO + lane_off;

    // ---- k path (B_hi cols 128..191), Z_fp16 . W_hi ----
    {
        const __half* q00 = d_q + (size_t)srow[0][0] * 64;
        const __half* q01 = d_q + (size_t)srow[0][1] * 64;
        const __half* q10 = d_q + (size_t)srow[1][0] * 64;
        const __half* q11 = d_q + (size_t)srow[1][1] * 64;

        float ps[2][2][4];
        #pragma unroll
        for (int mt = 0; mt < 2; mt++)
            #pragma unroll
            for (int r = 0; r < 2; r++)
                #pragma unroll
                for (int h = 0; h < 4; h++) ps[mt][r][h] = 0.f;

        #pragma unroll
        for (int j = 0; j < 8; j++) {
            float c0[4] = {0.f, 0.f, 0.f, 0.f};
            float c1[4] = {0.f, 0.f, 0.f, 0.f};
            #pragma unroll
            for (int ks = 0; ks < 4; ks++) {
                uint32_t bo = (uint32_t)(128 + 8 * j) * 144 + ks * 32;
                uint32_t bh[2];
                LDMX2(bh, bbh + bo);
                mma16816(c0, afh[0][ks], bh[0], bh[1]);
                mma16816(c1, afh[1][ks], bh[0], bh[1]);
            }
            int jc = 8 * j + 2 * t4;
            float2 qa = __half22float2(*(const __half2*)(q00 + jc));
            float2 qb = __half22float2(*(const __half2*)(q01 + jc));
            float2 qc = __half22float2(*(const __half2*)(q10 + jc));
            float2 qd = __half22float2(*(const __half2*)(q11 + jc));
            int h = j >> 1;
            ps[0][0][h] += c0[0] * qa.x + c0[1] * qa.y;
            ps[0][1][h] += c0[2] * qb.x + c0[3] * qb.y;
            ps[1][0][h] += c1[0] * qc.x + c1[1] * qc.y;
            ps[1][1][h] += c1[2] * qd.x + c1[3] * qd.y;
        }

        // quad-reduce + exp -> satt; denom scatter
        #pragma unroll
        for (int mt = 0; mt < 2; mt++)
            #pragma unroll
            for (int r = 0; r < 2; r++) {
                float v0 = ps[mt][r][0], v1 = ps[mt][r][1];
                float v2 = ps[mt][r][2], v3 = ps[mt][r][3];
                v0 += __shfl_xor_sync(0xffffffffu, v0, 1);
                v1 += __shfl_xor_sync(0xffffffffu, v1, 1);
                v2 += __shfl_xor_sync(0xffffffffu, v2, 1);
                v3 += __shfl_xor_sync(0xffffffffu, v3, 1);
                v0 += __shfl_xor_sync(0xffffffffu, v0, 2);
                v1 += __shfl_xor_sync(0xffffffffu, v1, 2);
                v2 += __shfl_xor_sync(0xffffffffu, v2, 2);
                v3 += __shfl_xor_sync(0xffffffffu, v3, 2);
                float a0 = __expf(v0 * 0.25f), a1 = __expf(v1 * 0.25f);
                float a2 = __expf(v2 * 0.25f), a3 = __expf(v3 * 0.25f);
                int row = rb + mt * 16 + g + 8 * r;
                if (t4 == 0)
                    *(float4*)&satt[row * 4] = make_float4(a0, a1, a2, a3);
                if (t4 == 1 && vrow[mt][r])
                    red4(&d_denom[(size_t)srow[mt][r] * 4], make_float4(a0, a1, a2, a3));
            }
    }
    __syncwarp();

    // ---- v | eo sweep (cols 0..127), Z_fp16 . (W_hi + W_lo), B shared across m-tiles ----
    bool even = ((t4 & 1) == 0);
    int colb = even ? (2 * t4) : (2 * (t4 - 1));   // 0 or 4
    int r = even ? 0 : 1;

    float a00 = 0.f, a01 = 0.f, a10 = 0.f, a11 = 0.f;

    #pragma unroll
    for (int j = 0; j < 16; j++) {
        if (j < 8 && (j & 1) == 0) {
            int h = j >> 1;
            a00 = satt[(rb + g) * 4 + h];
            a01 = satt[(rb + g + 8) * 4 + h];
            a10 = satt[(rb + 16 + g) * 4 + h];
            a11 = satt[(rb + 16 + g + 8) * 4 + h];
        }

        float c[2][4];
        #pragma unroll
        for (int mt = 0; mt < 2; mt++)
            #pragma unroll
            for (int i = 0; i < 4; i++) c[mt][i] = 0.f;

        #pragma unroll
        for (int ks = 0; ks < 4; ks++) {
            uint32_t bo = (uint32_t)(8 * j) * 144 + ks * 32;
            uint32_t bh[2], bl[2];
            LDMX2(bh, bbh + bo);
            LDMX2(bl, bbl + bo);
            mma16816(c[0], afh[0][ks], bh[0], bh[1]);
            mma16816(c[0], afh[0][ks], bl[0], bl[1]);
            mma16816(c[1], afh[1][ks], bh[0], bh[1]);
            mma16816(c[1], afh[1][ks], bl[0], bl[1]);
        }

        #pragma unroll
        for (int mt = 0; mt < 2; mt++) {
            float v0 = c[mt][0], v1 = c[mt][1], v2 = c[mt][2], v3 = c[mt][3];
            if (j < 8) {
                float s0 = (mt == 0) ? a00 : a10;
                float s1 = (mt == 0) ? a01 : a11;
                v0 *= s0; v1 *= s0; v2 *= s1; v3 *= s1;
            } else {
                int ec = 8 * (j - 8) + 2 * t4;
                float b0 = sbe[ec], b1 = sbe[ec + 1];
                v0 += b0; v1 += b1; v2 += b0; v3 += b1;
            }
            float o0 = __shfl_xor_sync(0xffffffffu, v0, 1);
            float o1 = __shfl_xor_sync(0xffffffffu, v1, 1);
            float o2 = __shfl_xor_sync(0xffffffffu, v2, 1);
            float o3 = __shfl_xor_sync(0xffffffffu, v3, 1);
            float4 vv = even ? make_float4(v0, v1, o0, o1)
                             : make_float4(o2, o3, v2, v3);
            if (vrow[mt][r]) {
                if (j < 8) {
                    red4(outp + (size_t)srow[mt][r] * 64 + 8 * j + colb, vv);
                } else {
                    long long row = ebase + rb + mt * 16 + g + 8 * r;
                    *(float4*)(eo + row * 64 + 8 * (j - 8) + colb) = vv;
                }
            }
        }
    }
}

// ================= kernel 3: normalize =================
__global__ void norm_kernel(float4* __restrict__ out, int Nn) {
    int i = blockIdx.x * blockDim.x + threadIdx.x;
    if (i >= Nn * 16) return;
    int n = i >> 4;
    int h = (i >> 2) & 3;
    float dinv = 1.0f / (d_denom[n * 4 + h] + 1e-16f);
    float4 v = out[i];
    v.x *= dinv; v.y *= dinv; v.z *= dinv; v.w *= dinv;
    out[i] = v;
}

// ================= launch =================
extern "C" void kernel_launch(void* const* d_in, const int* in_sizes, int n_in,
                              void* d_out, int out_size) {
    const float* x   = (const float*)d_in[0];
    const void*  eix = d_in[1];
    const float* ea  = (const float*)d_in[2];
    const float* Wq  = (const float*)d_in[3];
    const float* Wk  = (const float*)d_in[4];
    const float* Wv  = (const float*)d_in[5];
    const float* We  = (const float*)d_in[6];
    const float* be  = (const float*)d_in[7];

    int       Nn   = in_sizes[0] / 64;
    long long Etot = (long long)in_sizes[2] / 64;

    float* outp = (float*)d_out;
    float* eo   = outp + (size_t)Nn * 64;

    static int cfg = 0;
    if (!cfg) {
        cudaFuncSetAttribute(edge_kernel, cudaFuncAttributeMaxDynamicSharedMemorySize, SMEM_BYTES);
        cfg = 1;
    }

    setup_kernel<<<1184, 256>>>(x, (const int*)eix, Wq, Wv, We, Wk, (float4*)outp, Nn);
    int eblocks = (int)((Etot + EPB - 1) / EPB);
    edge_kernel<<<eblocks, NTHR, SMEM_BYTES>>>(x, eix, ea, be, outp, eo, Etot);
    norm_kernel<<<(Nn * 16 + 255) / 256, 256>>>((float4*)outp, Nn);
}

// round 16
// speedup vs baseline: 1.0984x; 1.0984x over previous
#include <cuda_runtime.h>
#include <cuda_fp16.h>
#include <cstdint>

#define MAXN 100000
#define EPB  256            // edges per block
#define NTHR 256

// ---------------- device scratch ----------------
__device__ __half d_q[(size_t)MAXN * 64];                // q[n][h*16+c] fp16, 12.8 MB
__device__ float d_denom[MAXN * 4];                      // per (node, head)
__device__ __align__(16) __half d_Bimg[2 * 192 * 72];    // [hi(192 cols) | lo(192 cols)][k pad 72]
__device__ int g_is64;

// ---------------- helpers ----------------
__device__ __forceinline__ void red4(float* p, float4 v) {
    asm volatile("red.global.add.v4.f32 [%0], {%1, %2, %3, %4};"
                 :: "l"(p), "f"(v.x), "f"(v.y), "f"(v.z), "f"(v.w) : "memory");
}
__device__ __forceinline__ long long load_idx(const void* p, long long i) {
    if (g_is64) return ((const long long*)p)[i];
    return (long long)((const int*)p)[i];
}
__device__ __forceinline__ uint32_t smem_u32(const void* p) {
    uint32_t a;
    asm("{ .reg .u64 t; cvta.to.shared.u64 t, %1; cvt.u32.u64 %0, t; }" : "=r"(a) : "l"(p));
    return a;
}
__device__ __forceinline__ uint32_t pack_h2(float a, float b) {
    __half2 h = __floats2half2_rn(a, b);
    return *(uint32_t*)&h;
}
__device__ __forceinline__ void mma16816(float c[4], const uint32_t a[4],
                                         uint32_t b0, uint32_t b1) {
    asm volatile("mma.sync.aligned.m16n8k16.row.col.f32.f16.f16.f32 "
                 "{%0,%1,%2,%3}, {%4,%5,%6,%7}, {%8,%9}, {%0,%1,%2,%3};"
                 : "+f"(c[0]), "+f"(c[1]), "+f"(c[2]), "+f"(c[3])
                 : "r"(a[0]), "r"(a[1]), "r"(a[2]), "r"(a[3]), "r"(b0), "r"(b1));
}
#define LDMX4(r, a)                                                        \
    asm volatile("ldmatrix.sync.aligned.m8n8.x4.shared.b16 {%0,%1,%2,%3}, [%4];" \
        : "=r"((r)[0]), "=r"((r)[1]), "=r"((r)[2]), "=r"((r)[3]) : "r"(a))
#define LDMX2(r, a)                                                        \
    asm volatile("ldmatrix.sync.aligned.m8n8.x2.shared.b16 {%0,%1}, [%2];" \
        : "=r"((r)[0]), "=r"((r)[1]) : "r"(a))

// ---------------- smem layout (bytes) — identical to R10/R14 ----------------
#define SM_SRC 0                       // int[256]            1024
#define SM_BE  1024                    // float[64]           256
#define SM_ATT 1280                    // float[256*4]        4096
#define SM_BHI 5376                    // half[192][72]       27648  (cols 0..191, hi)
#define SM_BLO 33024                   // half[128][72]       18432  (cols 0..127, lo)
#define SM_AHI 51456                   // half[256][72]       36864  (Z in plain fp16)
#define SMEM_BYTES 88320

// ================= kernel 1: fused setup (detect + zero + B image + q) =================
__global__ void __launch_bounds__(256) setup_kernel(const float* __restrict__ x,
                                                    const int*   __restrict__ eix32,
                                                    const float* __restrict__ Wq,
                                                    const float* __restrict__ Wv,
                                                    const float* __restrict__ We,
                                                    const float* __restrict__ Wk,
                                                    float4* __restrict__ out,
                                                    int Nn) {
    int t = threadIdx.x;

    // block 0: dtype detect + fp16 hi/lo split B image (cols 0..63 Wv, 64..127 We, 128..191 Wk)
    if (blockIdx.x == 0) {
        if (t == 0) {
            int any = 0;
            for (int i = 1; i < 256; i += 2) any |= eix32[i];
            g_is64 = (any == 0) ? 1 : 0;
        }
        if (t < 192) {
            int n = t;
            const float* W = (n < 64) ? Wv : ((n < 128) ? We : Wk);
            int nn = n & 63;
            for (int k = 0; k < 64; k++) {
                float w = W[k * 64 + nn];
                __half h = __float2half_rn(w);
                __half l = __float2half_rn(w - __half2float(h));
                d_Bimg[n * 72 + k]            = h;
                d_Bimg[192 * 72 + n * 72 + k] = l;
            }
        }
    }

    // zero out-accumulator + denom (grid-stride)
    {
        int i = blockIdx.x * blockDim.x + t;
        int st = gridDim.x * blockDim.x;
        float4 z = make_float4(0.f, 0.f, 0.f, 0.f);
        int n4 = Nn * 16;
        for (int j = i; j < n4; j += st) out[j] = z;
        float4* dn = (float4*)d_denom;
        for (int j = i; j < Nn; j += st) dn[j] = z;
    }

    // q = x @ Wq (fp16), grid-stride over node groups; Wq in fp16 smem (half2 reads, 1 wf)
    __shared__ __half2 sWq[64 * 32];   // [d][colpair], 8 KB
    for (int i = t; i < 1024; i += 256) {
        // i covers row i>>4, cols (i&15)*4
        float4 v = ((const float4*)Wq)[i];
        int row = i >> 4, cp = (i & 15) * 2;   // col pair index
        sWq[row * 32 + cp]     = __floats2half2_rn(v.x, v.y);
        sWq[row * 32 + cp + 1] = __floats2half2_rn(v.z, v.w);
    }
    __syncthreads();

    int warp = t >> 5, lane = t & 31;
    for (int n0 = blockIdx.x * 8; n0 < Nn; n0 += gridDim.x * 8) {
        int n = n0 + warp;
        if (n >= Nn) continue;
        float2 x2 = *(const float2*)&x[(size_t)n * 64 + 2 * lane];
        float qa = 0.f, qb = 0.f;
        #pragma unroll
        for (int dd = 0; dd < 32; dd++) {
            float xa = __shfl_sync(0xffffffffu, x2.x, dd);
            float xb = __shfl_sync(0xffffffffu, x2.y, dd);
            float2 w0 = __half22float2(sWq[(2 * dd) * 32 + lane]);
            float2 w1 = __half22float2(sWq[(2 * dd + 1) * 32 + lane]);
            qa += xa * w0.x + xb * w1.x;
            qb += xa * w0.y + xb * w1.y;
        }
        ((uint32_t*)d_q)[(size_t)n * 32 + lane] = pack_h2(qa, qb);
    }
}

// ================= kernel 2: fused edge pass (R14 — unchanged) =================
__global__ void __launch_bounds__(NTHR, 2) edge_kernel(const float* __restrict__ x,
                                                       const void*  __restrict__ eidx,
                                                       const float* __restrict__ ea,
                                                       const float* __restrict__ be,
                                                       float* __restrict__ outp,
                                                       float* __restrict__ eo,
                                                       long long Etot) {
    extern __shared__ __align__(16) char smem[];
    uint32_t smb = smem_u32(smem);
    int t = threadIdx.x, w = t >> 5, l = t & 31;
    int g = l >> 2, t4 = l & 3;

    int*   ssrc = (int*)(smem + SM_SRC);
    float* sbe  = (float*)(smem + SM_BE);
    float* satt = (float*)(smem + SM_ATT);

    long long ebase = (long long)blockIdx.x * EPB;

    // ---- B copy: contiguous prefix of d_Bimg = hi(1728 uint4) + lo cols 0..127 (1152 uint4) ----
    {
        const uint4* bs = (const uint4*)d_Bimg;
        uint4* bd = (uint4*)(smem + SM_BHI);
        #pragma unroll
        for (int i = 0; i < 12; i++) {
            int idx = t + NTHR * i;
            if (idx < 2880) bd[idx] = bs[idx];
        }
    }
    if (t < 64) sbe[t] = be[t];

    // ---- A build: 8 lanes per edge, coalesced. Z = ea * x[nbr] in plain fp16 ----
    {
        int oct = t & 7;
        int elb = t >> 3;                     // 0..31
        #pragma unroll
        for (int p = 0; p < 8; p++) {
            int eb = elb + 32 * p;            // edge within block
            long long e = ebase + eb;
            bool valid = (e < Etot);
            int src = 0; long long nbr = 0;
            if (valid) { src = (int)load_idx(eidx, e); nbr = load_idx(eidx, Etot + e); }
            if (oct == 0) ssrc[eb] = src;
            #pragma unroll
            for (int h2 = 0; h2 < 2; h2++) {
                float4 a4, x4;
                if (valid) {
                    a4 = *(const float4*)(ea + (size_t)e * 64 + h2 * 32 + oct * 4);
                    x4 = *(const float4*)(x + (size_t)nbr * 64 + h2 * 32 + oct * 4);
                } else {
                    a4 = make_float4(0.f, 0.f, 0.f, 0.f);
                    x4 = a4;
                }
                uint2 hv = make_uint2(pack_h2(a4.x * x4.x, a4.y * x4.y),
                                      pack_h2(a4.z * x4.z, a4.w * x4.w));
                *(uint2*)(smem + SM_AHI + (uint32_t)eb * 144 + h2 * 64 + oct * 8) = hv;
            }
        }
    }
    __syncthreads();

    // ---------------- per-warp: rows rb .. rb+31 (2 m-tiles) ----------------
    int rb = w * 32;

    int  srow[2][2];
    bool vrow[2][2];
    #pragma unroll
    for (int mt = 0; mt < 2; mt++)
        #pragma unroll
        for (int r = 0; r < 2; r++) {
            int row = rb + mt * 16 + g + 8 * r;
            srow[mt][r] = ssrc[row];
            vrow[mt][r] = (ebase + row) < Etot;
        }

    // ---- A fragments via ldmatrix.x4 (hi only) ----
    uint32_t afh[2][4][4];
    {
        uint32_t rowsel = (uint32_t)(l & 15);
        uint32_t koff = (uint32_t)(l >> 4) * 16;
        #pragma unroll
        for (int mt = 0; mt < 2; mt++) {
            uint32_t ab = smb + SM_AHI + (rb + mt * 16 + rowsel) * 144 + koff;
            #pragma unroll
            for (int ks = 0; ks < 4; ks++)
                LDMX4(afh[mt][ks], ab + ks * 32);
        }
    }

    // B per-lane bases (lanes 0-15 meaningful for x2)
    uint32_t lane_off = (uint32_t)(l & 7) * 144 + (uint32_t)((l >> 3) & 1) * 16;
    uint32_t bbh = smb + SM_BHI + lane_off;
    uint32_t bbl = smb + SM_BLO + lane_off;

    // ---- k path (B_hi cols 128..191), Z_fp16 . W_hi ----
    {
        const __half* q00 = d_q + (size_t)srow[0][0] * 64;
        const __half* q01 = d_q + (size_t)srow[0][1] * 64;
        const __half* q10 = d_q + (size_t)srow[1][0] * 64;
        const __half* q11 = d_q + (size_t)srow[1][1] * 64;

        float ps[2][2][4];
        #pragma unroll
        for (int mt = 0; mt < 2; mt++)
            #pragma unroll
            for (int r = 0; r < 2; r++)
                #pragma unroll
                for (int h = 0; h < 4; h++) ps[mt][r][h] = 0.f;

        #pragma unroll
        for (int j = 0; j < 8; j++) {
            float c0[4] = {0.f, 0.f, 0.f, 0.f};
            float c1[4] = {0.f, 0.f, 0.f, 0.f};
            #pragma unroll
            for (int ks = 0; ks < 4; ks++) {
                uint32_t bo = (uint32_t)(128 + 8 * j) * 144 + ks * 32;
                uint32_t bh[2];
                LDMX2(bh, bbh + bo);
                mma16816(c0, afh[0][ks], bh[0], bh[1]);
                mma16816(c1, afh[1][ks], bh[0], bh[1]);
            }
            int jc = 8 * j + 2 * t4;
            float2 qa = __half22float2(*(const __half2*)(q00 + jc));
            float2 qb = __half22float2(*(const __half2*)(q01 + jc));
            float2 qc = __half22float2(*(const __half2*)(q10 + jc));
            float2 qd = __half22float2(*(const __half2*)(q11 + jc));
            int h = j >> 1;
            ps[0][0][h] += c0[0] * qa.x + c0[1] * qa.y;
            ps[0][1][h] += c0[2] * qb.x + c0[3] * qb.y;
            ps[1][0][h] += c1[0] * qc.x + c1[1] * qc.y;
            ps[1][1][h] += c1[2] * qd.x + c1[3] * qd.y;
        }

        // quad-reduce + exp -> satt; denom scatter
        #pragma unroll
        for (int mt = 0; mt < 2; mt++)
            #pragma unroll
            for (int r = 0; r < 2; r++) {
                float v0 = ps[mt][r][0], v1 = ps[mt][r][1];
                float v2 = ps[mt][r][2], v3 = ps[mt][r][3];
                v0 += __shfl_xor_sync(0xffffffffu, v0, 1);
                v1 += __shfl_xor_sync(0xffffffffu, v1, 1);
                v2 += __shfl_xor_sync(0xffffffffu, v2, 1);
                v3 += __shfl_xor_sync(0xffffffffu, v3, 1);
                v0 += __shfl_xor_sync(0xffffffffu, v0, 2);
                v1 += __shfl_xor_sync(0xffffffffu, v1, 2);
                v2 += __shfl_xor_sync(0xffffffffu, v2, 2);
                v3 += __shfl_xor_sync(0xffffffffu, v3, 2);
                float a0 = __expf(v0 * 0.25f), a1 = __expf(v1 * 0.25f);
                float a2 = __expf(v2 * 0.25f), a3 = __expf(v3 * 0.25f);
                int row = rb + mt * 16 + g + 8 * r;
                if (t4 == 0)
                    *(float4*)&satt[row * 4] = make_float4(a0, a1, a2, a3);
                if (t4 == 1 && vrow[mt][r])
                    red4(&d_denom[(size_t)srow[mt][r] * 4], make_float4(a0, a1, a2, a3));
            }
    }
    __syncwarp();

    // ---- v | eo sweep (cols 0..127), Z_fp16 . (W_hi + W_lo), B shared across m-tiles ----
    bool even = ((t4 & 1) == 0);
    int colb = even ? (2 * t4) : (2 * (t4 - 1));   // 0 or 4
    int r = even ? 0 : 1;

    float a00 = 0.f, a01 = 0.f, a10 = 0.f, a11 = 0.f;

    #pragma unroll
    for (int j = 0; j < 16; j++) {
        if (j < 8 && (j & 1) == 0) {
            int h = j >> 1;
            a00 = satt[(rb + g) * 4 + h];
            a01 = satt[(rb + g + 8) * 4 + h];
            a10 = satt[(rb + 16 + g) * 4 + h];
            a11 = satt[(rb + 16 + g + 8) * 4 + h];
        }

        float c[2][4];
        #pragma unroll
        for (int mt = 0; mt < 2; mt++)
            #pragma unroll
            for (int i = 0; i < 4; i++) c[mt][i] = 0.f;

        #pragma unroll
        for (int ks = 0; ks < 4; ks++) {
            uint32_t bo = (uint32_t)(8 * j) * 144 + ks * 32;
            uint32_t bh[2], bl[2];
            LDMX2(bh, bbh + bo);
            LDMX2(bl, bbl + bo);
            mma16816(c[0], afh[0][ks], bh[0], bh[1]);
            mma16816(c[0], afh[0][ks], bl[0], bl[1]);
            mma16816(c[1], afh[1][ks], bh[0], bh[1]);
            mma16816(c[1], afh[1][ks], bl[0], bl[1]);
        }

        #pragma unroll
        for (int mt = 0; mt < 2; mt++) {
            float v0 = c[mt][0], v1 = c[mt][1], v2 = c[mt][2], v3 = c[mt][3];
            if (j < 8) {
                float s0 = (mt == 0) ? a00 : a10;
                float s1 = (mt == 0) ? a01 : a11;
                v0 *= s0; v1 *= s0; v2 *= s1; v3 *= s1;
            } else {
                int ec = 8 * (j - 8) + 2 * t4;
                float b0 = sbe[ec], b1 = sbe[ec + 1];
                v0 += b0; v1 += b1; v2 += b0; v3 += b1;
            }
            float o0 = __shfl_xor_sync(0xffffffffu, v0, 1);
            float o1 = __shfl_xor_sync(0xffffffffu, v1, 1);
            float o2 = __shfl_xor_sync(0xffffffffu, v2, 1);
            float o3 = __shfl_xor_sync(0xffffffffu, v3, 1);
            float4 vv = even ? make_float4(v0, v1, o0, o1)
                             : make_float4(o2, o3, v2, v3);
            if (vrow[mt][r]) {
                if (j < 8) {
                    red4(outp + (size_t)srow[mt][r] * 64 + 8 * j + colb, vv);
                } else {
                    long long row = ebase + rb + mt * 16 + g + 8 * r;
                    *(float4*)(eo + row * 64 + 8 * (j - 8) + colb) = vv;
                }
            }
        }
    }
}

// ================= kernel 3: normalize =================
__global__ void norm_kernel(float4* __restrict__ out, int Nn) {
    int i = blockIdx.x * blockDim.x + threadIdx.x;
    if (i >= Nn * 16) return;
    int n = i >> 4;
    int h = (i >> 2) & 3;
    float dinv = 1.0f / (d_denom[n * 4 + h] + 1e-16f);
    float4 v = out[i];
    v.x *= dinv; v.y *= dinv; v.z *= dinv; v.w *= dinv;
    out[i] = v;
}

// ================= launch =================
extern "C" void kernel_launch(void* const* d_in, const int* in_sizes, int n_in,
                              void* d_out, int out_size) {
    const float* x   = (const float*)d_in[0];
    const void*  eix = d_in[1];
    const float* ea  = (const float*)d_in[2];
    const float* Wq  = (const float*)d_in[3];
    const float* Wk  = (const float*)d_in[4];
    const float* Wv  = (const float*)d_in[5];
    const float* We  = (const float*)d_in[6];
    const float* be  = (const float*)d_in[7];

    int       Nn   = in_sizes[0] / 64;
    long long Etot = (long long)in_sizes[2] / 64;

    float* outp = (float*)d_out;
    float* eo   = outp + (size_t)Nn * 64;

    static int cfg = 0;
    if (!cfg) {
        cudaFuncSetAttribute(edge_kernel, cudaFuncAttributeMaxDynamicSharedMemorySize, SMEM_BYTES);
        cfg = 1;
    }

    setup_kernel<<<1184, 256>>>(x, (const int*)eix, Wq, Wv, We, Wk, (float4*)outp, Nn);
    int eblocks = (int)((Etot + EPB - 1) / EPB);
    edge_kernel<<<eblocks, NTHR, SMEM_BYTES>>>(x, eix, ea, be, outp, eo, Etot);
    norm_kernel<<<(Nn * 16 + 255) / 256, 256>>>((float4*)outp, Nn);
}

// round 17
// speedup vs baseline: 1.1528x; 1.0495x over previous
#include <cuda_runtime.h>
#include <cuda_fp16.h>
#include <cstdint>

#define MAXN 100000
#define EPB  256            // edges per block
#define NTHR 256

// ---------------- device scratch ----------------
__device__ __half d_q[(size_t)MAXN * 64];                // q[n][h*16+c] fp16, 12.8 MB
__device__ float d_denom[MAXN * 4];                      // per (node, head)
__device__ __align__(16) __half d_Bimg[2 * 192 * 72];    // [hi(192 cols) | lo(192 cols)][k pad 72]
__device__ int g_is64;

// ---------------- helpers ----------------
__device__ __forceinline__ void red4(float* p, float4 v) {
    asm volatile("red.global.add.v4.f32 [%0], {%1, %2, %3, %4};"
                 :: "l"(p), "f"(v.x), "f"(v.y), "f"(v.z), "f"(v.w) : "memory");
}
__device__ __forceinline__ long long load_idx(const void* p, long long i) {
    if (g_is64) return ((const long long*)p)[i];
    return (long long)((const int*)p)[i];
}
__device__ __forceinline__ uint32_t smem_u32(const void* p) {
    uint32_t a;
    asm("{ .reg .u64 t; cvta.to.shared.u64 t, %1; cvt.u32.u64 %0, t; }" : "=r"(a) : "l"(p));
    return a;
}
__device__ __forceinline__ uint32_t pack_h2(float a, float b) {
    __half2 h = __floats2half2_rn(a, b);
    return *(uint32_t*)&h;
}
__device__ __forceinline__ void mma16816(float c[4], const uint32_t a[4],
                                         uint32_t b0, uint32_t b1) {
    asm volatile("mma.sync.aligned.m16n8k16.row.col.f32.f16.f16.f32 "
                 "{%0,%1,%2,%3}, {%4,%5,%6,%7}, {%8,%9}, {%0,%1,%2,%3};"
                 : "+f"(c[0]), "+f"(c[1]), "+f"(c[2]), "+f"(c[3])
                 : "r"(a[0]), "r"(a[1]), "r"(a[2]), "r"(a[3]), "r"(b0), "r"(b1));
}
#define LDMX4(r, a)                                                        \
    asm volatile("ldmatrix.sync.aligned.m8n8.x4.shared.b16 {%0,%1,%2,%3}, [%4];" \
        : "=r"((r)[0]), "=r"((r)[1]), "=r"((r)[2]), "=r"((r)[3]) : "r"(a))
#define LDMX2(r, a)                                                        \
    asm volatile("ldmatrix.sync.aligned.m8n8.x2.shared.b16 {%0,%1}, [%2];" \
        : "=r"((r)[0]), "=r"((r)[1]) : "r"(a))

// ---------------- edge smem layout (bytes) — identical to R10/R14/R16 ----------------
#define SM_SRC 0                       // int[256]            1024
#define SM_BE  1024                    // float[64]           256
#define SM_ATT 1280                    // float[256*4]        4096
#define SM_BHI 5376                    // half[192][72]       27648  (cols 0..191, hi)
#define SM_BLO 33024                   // half[128][72]       18432  (cols 0..127, lo)
#define SM_AHI 51456                   // half[256][72]       36864  (Z in plain fp16)
#define SMEM_BYTES 88320

// ================= kernel 1: fused setup (detect + zero + B image + q via mma) =================
__global__ void __launch_bounds__(256) setup_kernel(const float* __restrict__ x,
                                                    const int*   __restrict__ eix32,
                                                    const float* __restrict__ Wq,
                                                    const float* __restrict__ Wv,
                                                    const float* __restrict__ We,
                                                    const float* __restrict__ Wk,
                                                    float4* __restrict__ out,
                                                    int Nn) {
    int t = threadIdx.x;

    // block 0: dtype detect + fp16 hi/lo split B image (cols 0..63 Wv, 64..127 We, 128..191 Wk)
    if (blockIdx.x == 0) {
        if (t == 0) {
            int any = 0;
            for (int i = 1; i < 256; i += 2) any |= eix32[i];
            g_is64 = (any == 0) ? 1 : 0;
        }
        if (t < 192) {
            int n = t;
            const float* W = (n < 64) ? Wv : ((n < 128) ? We : Wk);
            int nn = n & 63;
            for (int k = 0; k < 64; k++) {
                float w = W[k * 64 + nn];
                __half h = __float2half_rn(w);
                __half l = __float2half_rn(w - __half2float(h));
                d_Bimg[n * 72 + k]            = h;
                d_Bimg[192 * 72 + n * 72 + k] = l;
            }
        }
    }

    // zero out-accumulator + denom (grid-stride)
    {
        int i = blockIdx.x * blockDim.x + t;
        int st = gridDim.x * blockDim.x;
        float4 z = make_float4(0.f, 0.f, 0.f, 0.f);
        int n4 = Nn * 16;
        for (int j = i; j < n4; j += st) out[j] = z;
        float4* dn = (float4*)d_denom;
        for (int j = i; j < Nn; j += st) dn[j] = z;
    }

    // ---- q = x @ Wq via tensor cores: 128-node tiles, (x_hi + x_lo) @ Wq_hi ----
    __shared__ __align__(16) __half sxh[128 * 72];   // 18432 B
    __shared__ __align__(16) __half sxl[128 * 72];   // 18432 B
    __shared__ __align__(16) __half swq[64 * 72];    // 9216 B  (B image: [col][k])
    uint32_t sxh_b = smem_u32(sxh);
    uint32_t sxl_b = smem_u32(sxl);
    uint32_t swq_b = smem_u32(swq);

    // build Wq B image (transposed, fp16)
    for (int i = t; i < 4096; i += 256) {
        int k = i >> 6, col = i & 63;
        swq[col * 72 + k] = __float2half_rn(Wq[i]);
    }

    int w = t >> 5, l = t & 31;
    int g = l >> 2, t4 = l & 3;

    for (int n0 = blockIdx.x * 128; n0 < Nn; n0 += gridDim.x * 128) {
        __syncthreads();
        // stage x tile (128 rows x 64 floats), hi/lo split, coalesced
        for (int i = t; i < 2048; i += 256) {
            int row = i >> 4, f4 = i & 15;
            float4 v = (n0 + row < Nn) ? ((const float4*)x)[(size_t)(n0 + row) * 16 + f4]
                                       : make_float4(0.f, 0.f, 0.f, 0.f);
            float h0 = __half2float(__float2half_rn(v.x));
            float h1 = __half2float(__float2half_rn(v.y));
            float h2 = __half2float(__float2half_rn(v.z));
            float h3 = __half2float(__float2half_rn(v.w));
            uint2 hv = make_uint2(pack_h2(v.x, v.y), pack_h2(v.z, v.w));
            uint2 lv = make_uint2(pack_h2(v.x - h0, v.y - h1), pack_h2(v.z - h2, v.w - h3));
            uint32_t off = (uint32_t)row * 144 + f4 * 8;
            *(uint2*)((char*)sxh + off) = hv;
            *(uint2*)((char*)sxl + off) = lv;
        }
        __syncthreads();

        // A fragments (rows w*16 .. w*16+15)
        uint32_t afh[4][4], afl[4][4];
        {
            uint32_t rowsel = (uint32_t)(l & 15);
            uint32_t koff = (uint32_t)(l >> 4) * 16;
            uint32_t ah = sxh_b + (w * 16 + rowsel) * 144 + koff;
            uint32_t al = sxl_b + (w * 16 + rowsel) * 144 + koff;
            #pragma unroll
            for (int ks = 0; ks < 4; ks++) {
                LDMX4(afh[ks], ah + ks * 32);
                LDMX4(afl[ks], al + ks * 32);
            }
        }

        uint32_t bb = swq_b + (uint32_t)(l & 7) * 144 + (uint32_t)((l >> 3) & 1) * 16;

        int nr0 = n0 + w * 16 + g;
        int nr1 = nr0 + 8;
        bool v0 = nr0 < Nn, v1 = nr1 < Nn;

        #pragma unroll
        for (int j = 0; j < 8; j++) {
            float c[4] = {0.f, 0.f, 0.f, 0.f};
            #pragma unroll
            for (int ks = 0; ks < 4; ks++) {
                uint32_t bo = (uint32_t)(8 * j) * 144 + ks * 32;
                uint32_t bh[2];
                LDMX2(bh, bb + bo);
                mma16816(c, afh[ks], bh[0], bh[1]);
                mma16816(c, afl[ks], bh[0], bh[1]);
            }
            int col2 = 4 * j + t4;   // half2 index of cols 8j+2t4, +1
            if (v0) ((uint32_t*)d_q)[(size_t)nr0 * 32 + col2] = pack_h2(c[0], c[1]);
            if (v1) ((uint32_t*)d_q)[(size_t)nr1 * 32 + col2] = pack_h2(c[2], c[3]);
        }
    }
}

// ================= kernel 2: fused edge pass (R14/R16 — unchanged) =================
__global__ void __launch_bounds__(NTHR, 2) edge_kernel(const float* __restrict__ x,
                                                       const void*  __restrict__ eidx,
                                                       const float* __restrict__ ea,
                                                       const float* __restrict__ be,
                                                       float* __restrict__ outp,
                                                       float* __restrict__ eo,
                                                       long long Etot) {
    extern __shared__ __align__(16) char smem[];
    uint32_t smb = smem_u32(smem);
    int t = threadIdx.x, w = t >> 5, l = t & 31;
    int g = l >> 2, t4 = l & 3;

    int*   ssrc = (int*)(smem + SM_SRC);
    float* sbe  = (float*)(smem + SM_BE);
    float* satt = (float*)(smem + SM_ATT);

    long long ebase = (long long)blockIdx.x * EPB;

    // ---- B copy: contiguous prefix of d_Bimg = hi(1728 uint4) + lo cols 0..127 (1152 uint4) ----
    {
        const uint4* bs = (const uint4*)d_Bimg;
        uint4* bd = (uint4*)(smem + SM_BHI);
        #pragma unroll
        for (int i = 0; i < 12; i++) {
            int idx = t + NTHR * i;
            if (idx < 2880) bd[idx] = bs[idx];
        }
    }
    if (t < 64) sbe[t] = be[t];

    // ---- A build: 8 lanes per edge, coalesced. Z = ea * x[nbr] in plain fp16 ----
    {
        int oct = t & 7;
        int elb = t >> 3;                     // 0..31
        #pragma unroll
        for (int p = 0; p < 8; p++) {
            int eb = elb + 32 * p;            // edge within block
            long long e = ebase + eb;
            bool valid = (e < Etot);
            int src = 0; long long nbr = 0;
            if (valid) { src = (int)load_idx(eidx, e); nbr = load_idx(eidx, Etot + e); }
            if (oct == 0) ssrc[eb] = src;
            #pragma unroll
            for (int h2 = 0; h2 < 2; h2++) {
                float4 a4, x4;
                if (valid) {
                    a4 = *(const float4*)(ea + (size_t)e * 64 + h2 * 32 + oct * 4);
                    x4 = *(const float4*)(x + (size_t)nbr * 64 + h2 * 32 + oct * 4);
                } else {
                    a4 = make_float4(0.f, 0.f, 0.f, 0.f);
                    x4 = a4;
                }
                uint2 hv = make_uint2(pack_h2(a4.x * x4.x, a4.y * x4.y),
                                      pack_h2(a4.z * x4.z, a4.w * x4.w));
                *(uint2*)(smem + SM_AHI + (uint32_t)eb * 144 + h2 * 64 + oct * 8) = hv;
            }
        }
    }
    __syncthreads();

    // ---------------- per-warp: rows rb .. rb+31 (2 m-tiles) ----------------
    int rb = w * 32;

    int  srow[2][2];
    bool vrow[2][2];
    #pragma unroll
    for (int mt = 0; mt < 2; mt++)
        #pragma unroll
        for (int r = 0; r < 2; r++) {
            int row = rb + mt * 16 + g + 8 * r;
            srow[mt][r] = ssrc[row];
            vrow[mt][r] = (ebase + row) < Etot;
        }

    // ---- A fragments via ldmatrix.x4 (hi only) ----
    uint32_t afh[2][4][4];
    {
        uint32_t rowsel = (uint32_t)(l & 15);
        uint32_t koff = (uint32_t)(l >> 4) * 16;
        #pragma unroll
        for (int mt = 0; mt < 2; mt++) {
            uint32_t ab = smb + SM_AHI + (rb + mt * 16 + rowsel) * 144 + koff;
            #pragma unroll
            for (int ks = 0; ks < 4; ks++)
                LDMX4(afh[mt][ks], ab + ks * 32);
        }
    }

    // B per-lane bases (lanes 0-15 meaningful for x2)
    uint32_t lane_off = (uint32_t)(l & 7) * 144 + (uint32_t)((l >> 3) & 1) * 16;
    uint32_t bbh = smb + SM_BHI + lane_off;
    uint32_t bbl = smb + SM_BLO + lane_off;

    // ---- k path (B_hi cols 128..191), Z_fp16 . W_hi ----
    {
        const __half* q00 = d_q + (size_t)srow[0][0] * 64;
        const __half* q01 = d_q + (size_t)srow[0][1] * 64;
        const __half* q10 = d_q + (size_t)srow[1][0] * 64;
        const __half* q11 = d_q + (size_t)srow[1][1] * 64;

        float ps[2][2][4];
        #pragma unroll
        for (int mt = 0; mt < 2; mt++)
            #pragma unroll
            for (int r = 0; r < 2; r++)
                #pragma unroll
                for (int h = 0; h < 4; h++) ps[mt][r][h] = 0.f;

        #pragma unroll
        for (int j = 0; j < 8; j++) {
            float c0[4] = {0.f, 0.f, 0.f, 0.f};
            float c1[4] = {0.f, 0.f, 0.f, 0.f};
            #pragma unroll
            for (int ks = 0; ks < 4; ks++) {
                uint32_t bo = (uint32_t)(128 + 8 * j) * 144 + ks * 32;
                uint32_t bh[2];
                LDMX2(bh, bbh + bo);
                mma16816(c0, afh[0][ks], bh[0], bh[1]);
                mma16816(c1, afh[1][ks], bh[0], bh[1]);
            }
            int jc = 8 * j + 2 * t4;
            float2 qa = __half22float2(*(const __half2*)(q00 + jc));
            float2 qb = __half22float2(*(const __half2*)(q01 + jc));
            float2 qc = __half22float2(*(const __half2*)(q10 + jc));
            float2 qd = __half22float2(*(const __half2*)(q11 + jc));
            int h = j >> 1;
            ps[0][0][h] += c0[0] * qa.x + c0[1] * qa.y;
            ps[0][1][h] += c0[2] * qb.x + c0[3] * qb.y;
            ps[1][0][h] += c1[0] * qc.x + c1[1] * qc.y;
            ps[1][1][h] += c1[2] * qd.x + c1[3] * qd.y;
        }

        // quad-reduce + exp -> satt; denom scatter
        #pragma unroll
        for (int mt = 0; mt < 2; mt++)
            #pragma unroll
            for (int r = 0; r < 2; r++) {
                float v0 = ps[mt][r][0], v1 = ps[mt][r][1];
                float v2 = ps[mt][r][2], v3 = ps[mt][r][3];
                v0 += __shfl_xor_sync(0xffffffffu, v0, 1);
                v1 += __shfl_xor_sync(0xffffffffu, v1, 1);
                v2 += __shfl_xor_sync(0xffffffffu, v2, 1);
                v3 += __shfl_xor_sync(0xffffffffu, v3, 1);
                v0 += __shfl_xor_sync(0xffffffffu, v0, 2);
                v1 += __shfl_xor_sync(0xffffffffu, v1, 2);
                v2 += __shfl_xor_sync(0xffffffffu, v2, 2);
                v3 += __shfl_xor_sync(0xffffffffu, v3, 2);
                float a0 = __expf(v0 * 0.25f), a1 = __expf(v1 * 0.25f);
                float a2 = __expf(v2 * 0.25f), a3 = __expf(v3 * 0.25f);
                int row = rb + mt * 16 + g + 8 * r;
                if (t4 == 0)
                    *(float4*)&satt[row * 4] = make_float4(a0, a1, a2, a3);
                if (t4 == 1 && vrow[mt][r])
                    red4(&d_denom[(size_t)srow[mt][r] * 4], make_float4(a0, a1, a2, a3));
            }
    }
    __syncwarp();

    // ---- v | eo sweep (cols 0..127), Z_fp16 . (W_hi + W_lo), B shared across m-tiles ----
    bool even = ((t4 & 1) == 0);
    int colb = even ? (2 * t4) : (2 * (t4 - 1));   // 0 or 4
    int r = even ? 0 : 1;

    float a00 = 0.f, a01 = 0.f, a10 = 0.f, a11 = 0.f;

    #pragma unroll
    for (int j = 0; j < 16; j++) {
        if (j < 8 && (j & 1) == 0) {
            int h = j >> 1;
            a00 = satt[(rb + g) * 4 + h];
            a01 = satt[(rb + g + 8) * 4 + h];
            a10 = satt[(rb + 16 + g) * 4 + h];
            a11 = satt[(rb + 16 + g + 8) * 4 + h];
        }

        float c[2][4];
        #pragma unroll
        for (int mt = 0; mt < 2; mt++)
            #pragma unroll
            for (int i = 0; i < 4; i++) c[mt][i] = 0.f;

        #pragma unroll
        for (int ks = 0; ks < 4; ks++) {
            uint32_t bo = (uint32_t)(8 * j) * 144 + ks * 32;
            uint32_t bh[2], bl[2];
            LDMX2(bh, bbh + bo);
            LDMX2(bl, bbl + bo);
            mma16816(c[0], afh[0][ks], bh[0], bh[1]);
            mma16816(c[0], afh[0][ks], bl[0], bl[1]);
            mma16816(c[1], afh[1][ks], bh[0], bh[1]);
            mma16816(c[1], afh[1][ks], bl[0], bl[1]);
        }

        #pragma unroll
        for (int mt = 0; mt < 2; mt++) {
            float v0 = c[mt][0], v1 = c[mt][1], v2 = c[mt][2], v3 = c[mt][3];
            if (j < 8) {
                float s0 = (mt == 0) ? a00 : a10;
                float s1 = (mt == 0) ? a01 : a11;
                v0 *= s0; v1 *= s0; v2 *= s1; v3 *= s1;
            } else {
                int ec = 8 * (j - 8) + 2 * t4;
                float b0 = sbe[ec], b1 = sbe[ec + 1];
                v0 += b0; v1 += b1; v2 += b0; v3 += b1;
            }
            float o0 = __shfl_xor_sync(0xffffffffu, v0, 1);
            float o1 = __shfl_xor_sync(0xffffffffu, v1, 1);
            float o2 = __shfl_xor_sync(0xffffffffu, v2, 1);
            float o3 = __shfl_xor_sync(0xffffffffu, v3, 1);
            float4 vv = even ? make_float4(v0, v1, o0, o1)
                             : make_float4(o2, o3, v2, v3);
            if (vrow[mt][r]) {
                if (j < 8) {
                    red4(outp + (size_t)srow[mt][r] * 64 + 8 * j + colb, vv);
                } else {
                    long long row = ebase + rb + mt * 16 + g + 8 * r;
                    *(float4*)(eo + row * 64 + 8 * (j - 8) + colb) = vv;
                }
            }
        }
    }
}

// ================= kernel 3: normalize =================
__global__ void norm_kernel(float4* __restrict__ out, int Nn) {
    int i = blockIdx.x * blockDim.x + threadIdx.x;
    if (i >= Nn * 16) return;
    int n = i >> 4;
    int h = (i >> 2) & 3;
    float dinv = 1.0f / (d_denom[n * 4 + h] + 1e-16f);
    float4 v = out[i];
    v.x *= dinv; v.y *= dinv; v.z *= dinv; v.w *= dinv;
    out[i] = v;
}

// ================= launch =================
extern "C" void kernel_launch(void* const* d_in, const int* in_sizes, int n_in,
                              void* d_out, int out_size) {
    const float* x   = (const float*)d_in[0];
    const void*  eix = d_in[1];
    const float* ea  = (const float*)d_in[2];
    const float* Wq  = (const float*)d_in[3];
    const float* Wk  = (const float*)d_in[4];
    const float* Wv  = (const float*)d_in[5];
    const float* We  = (const float*)d_in[6];
    const float* be  = (const float*)d_in[7];

    int       Nn   = in_sizes[0] / 64;
    long long Etot = (long long)in_sizes[2] / 64;

    float* outp = (float*)d_out;
    float* eo   = outp + (size_t)Nn * 64;

    static int cfg = 0;
    if (!cfg) {
        cudaFuncSetAttribute(edge_kernel, cudaFuncAttributeMaxDynamicSharedMemorySize, SMEM_BYTES);
        cfg = 1;
    }

    setup_kernel<<<1184, 256>>>(x, (const int*)eix, Wq, Wv, We, Wk, (float4*)outp, Nn);
    int eblocks = (int)((Etot + EPB - 1) / EPB);
    edge_kernel<<<eblocks, NTHR, SMEM_BYTES>>>(x, eix, ea, be, outp, eo, Etot);
    norm_kernel<<<(Nn * 16 + 255) / 256, 256>>>((float4*)outp, Nn);
}